// round 1
// baseline (speedup 1.0000x reference)
#include <cuda_runtime.h>

// Problem constants (fixed shapes from reference):
// U_hat:   (32,14,14,2,16,32)        = 6,422,528 f32
// W_t:     (1,2,16,32,8)             = 8,192 f32
// W_affine:(1,1,2,16,32,8)           = 8,192 f32
// Outputs: C (B,S1,S2,NC,DC,F,I) then U_hat_I (same shape), concatenated.
#define NROWS   200704      // 32*14*14*2*16
#define OUT_ELEMS 51380224  // NROWS * 32 * 8
#define WPB     8           // warps per block

__global__ __launch_bounds__(256, 8)
void mhsa_kernel(const float* __restrict__ U,
                 const float* __restrict__ Wt,
                 const float* __restrict__ Wa,
                 float* __restrict__ outC,
                 float* __restrict__ outU)
{
    const int warp = blockIdx.x * WPB + (threadIdx.x >> 5);
    // grid sized exactly: 200704 / 8 warps per block = 25088 blocks, no remainder
    const int f = threadIdx.x & 31;

    // Load this row's U value for lane's f (warp reads 128 contiguous bytes)
    const float u = U[warp * 32 + f];

    // Weight slice for (nc,dc) = row % 32; per lane 8 contiguous floats at f*8
    const int woff = (warp & 31) * 256 + f * 8;
    const float4 wa0 = *reinterpret_cast<const float4*>(Wa + woff);
    const float4 wa1 = *reinterpret_cast<const float4*>(Wa + woff + 4);
    const float4 wt0 = *reinterpret_cast<const float4*>(Wt + woff);
    const float4 wt1 = *reinterpret_cast<const float4*>(Wt + woff + 4);

    float wa[8] = {wa0.x, wa0.y, wa0.z, wa0.w, wa1.x, wa1.y, wa1.z, wa1.w};
    float wt[8] = {wt0.x, wt0.y, wt0.z, wt0.w, wt1.x, wt1.y, wt1.z, wt1.w};

    // U_hat_I and its square (per-i)
    float uhi[8], ss[8], mw[8];
    #pragma unroll
    for (int i = 0; i < 8; i++) {
        uhi[i] = u * wa[i];
        ss[i]  = uhi[i] * uhi[i];
        mw[i]  = wt[i];
    }

    // Store U_hat_I (lane writes 32 contiguous bytes; warp covers 1024B)
    {
        float4 s0 = make_float4(uhi[0], uhi[1], uhi[2], uhi[3]);
        float4 s1 = make_float4(uhi[4], uhi[5], uhi[6], uhi[7]);
        float* p = outU + (size_t)warp * 256 + f * 8;
        *reinterpret_cast<float4*>(p)     = s0;
        *reinterpret_cast<float4*>(p + 4) = s1;
    }

    // Butterfly: sum of squares over f (diag) and max of Wt over f, fused
    #pragma unroll
    for (int s = 16; s > 0; s >>= 1) {
        #pragma unroll
        for (int i = 0; i < 8; i++) {
            ss[i] += __shfl_xor_sync(0xffffffffu, ss[i], s);
            mw[i]  = fmaxf(mw[i], __shfl_xor_sync(0xffffffffu, mw[i], s));
        }
    }

    // diag_i = sumsq / sqrt(16) = sumsq * 0.25
    // A[f,i] = diag_i * Wt[f,i]; since diag >= 0, max_f A = diag * max_f Wt
    float e[8];
    #pragma unroll
    for (int i = 0; i < 8; i++) {
        float diag = ss[i] * 0.25f;
        e[i] = __expf(diag * (wt[i] - mw[i]));
    }

    // Butterfly: sum of exp over f
    float se[8];
    #pragma unroll
    for (int i = 0; i < 8; i++) se[i] = e[i];
    #pragma unroll
    for (int s = 16; s > 0; s >>= 1) {
        #pragma unroll
        for (int i = 0; i < 8; i++)
            se[i] += __shfl_xor_sync(0xffffffffu, se[i], s);
    }

    float c[8];
    #pragma unroll
    for (int i = 0; i < 8; i++) c[i] = e[i] * (1.0f / se[i]);

    {
        float4 s0 = make_float4(c[0], c[1], c[2], c[3]);
        float4 s1 = make_float4(c[4], c[5], c[6], c[7]);
        float* p = outC + (size_t)warp * 256 + f * 8;
        *reinterpret_cast<float4*>(p)     = s0;
        *reinterpret_cast<float4*>(p + 4) = s1;
    }
}

extern "C" void kernel_launch(void* const* d_in, const int* in_sizes, int n_in,
                              void* d_out, int out_size)
{
    const float* U  = (const float*)d_in[0];   // U_hat
    const float* Wt = (const float*)d_in[1];   // W_t
    const float* Wa = (const float*)d_in[2];   // W_affine
    float* outC = (float*)d_out;               // C first
    float* outU = (float*)d_out + OUT_ELEMS;   // then U_hat_I

    const int blocks = NROWS / WPB;            // 25088, exact
    mhsa_kernel<<<blocks, WPB * 32>>>(U, Wt, Wa, outC, outU);
}

// round 3
// speedup vs baseline: 1.3406x; 1.3406x over previous
#include <cuda_runtime.h>

// Shapes (fixed):
// U_hat:   (32,14,14,2,16,32)  = 6,422,528 f32   -> NROWS=200704 rows of 32 (f)
// W_t:     (2,16,32,8)         = 8,192 f32       -> 32 slices (nc*dc) of [f=32][i=8]
// W_affine:(2,16,32,8)         = 8,192 f32
// Output:  C (NROWS,32,8) then U_hat_I (NROWS,32,8), concatenated.
#define NROWS          200704
#define OUT_ELEMS      51380224   // NROWS*256
#define ROWS_PER_SLICE 6272       // NROWS/32
#define NBLOCKS        1184       // 148 SMs * 8  (2 exact waves at 4 blocks/SM)
#define WPB            8
#define NWARPS         (NBLOCKS*WPB)          // 9472
#define WARPS_PER_SLICE (NWARPS/32)           // 296

__device__ __forceinline__ float ex2_approx(float x) {
    float r;
    asm("ex2.approx.ftz.f32 %0, %1;" : "=f"(r) : "f"(x));
    return r;
}

__global__ __launch_bounds__(256, 4)
void mhsa_kernel(const float* __restrict__ U,
                 const float* __restrict__ Wt,
                 const float* __restrict__ Wa,
                 float* __restrict__ outC,
                 float* __restrict__ outU)
{
    const int w = blockIdx.x * WPB + (threadIdx.x >> 5);  // 0..9471
    const int f = threadIdx.x & 31;
    const int c = w & 31;        // (nc,dc) slice, 32 values
    const int g = w >> 5;        // 0..295 warp-within-slice

    // ---- one-time per warp: weights into registers ----
    const int woff = c * 256 + f * 8;
    const float4 wa0 = *reinterpret_cast<const float4*>(Wa + woff);
    const float4 wa1 = *reinterpret_cast<const float4*>(Wa + woff + 4);
    const float4 wt0 = *reinterpret_cast<const float4*>(Wt + woff);
    const float4 wt1 = *reinterpret_cast<const float4*>(Wt + woff + 4);
    float wa[8] = {wa0.x, wa0.y, wa0.z, wa0.w, wa1.x, wa1.y, wa1.z, wa1.w};
    float wt[8] = {wt0.x, wt0.y, wt0.z, wt0.w, wt1.x, wt1.y, wt1.z, wt1.w};

    // max over f of Wt (per i), once per warp
    float mw[8];
    #pragma unroll
    for (int i = 0; i < 8; i++) mw[i] = wt[i];
    #pragma unroll
    for (int s = 16; s > 0; s >>= 1)
        #pragma unroll
        for (int i = 0; i < 8; i++)
            mw[i] = fmaxf(mw[i], __shfl_xor_sync(0xffffffffu, mw[i], s));

    // wtl2[i] = 0.25 * log2(e) * (wt - mw)   (diag >= 0, so max_f A = diag*mw)
    float wtl2[8];
    const float k = 0.25f * 1.4426950408889634f;
    #pragma unroll
    for (int i = 0; i < 8; i++) wtl2[i] = k * (wt[i] - mw[i]);

    // ---- stream rows of this slice: row = kk*32 + c ----
    for (int kk = g; kk < ROWS_PER_SLICE; kk += WARPS_PER_SLICE) {
        const int row = (kk << 5) + c;
        const float u = __ldcs(U + (size_t)row * 32 + f);

        float uhi[8], ss[8];
        #pragma unroll
        for (int i = 0; i < 8; i++) {
            uhi[i] = u * wa[i];
            ss[i]  = uhi[i] * uhi[i];
        }

        // store U_hat_I (lane writes 32 contiguous bytes; warp 1024B coalesced)
        {
            float* p = outU + (size_t)row * 256 + f * 8;
            __stcs(reinterpret_cast<float4*>(p),
                   make_float4(uhi[0], uhi[1], uhi[2], uhi[3]));
            __stcs(reinterpret_cast<float4*>(p + 4),
                   make_float4(uhi[4], uhi[5], uhi[6], uhi[7]));
        }

        // butterfly sum over f: ss[i] -> sum of squares (diag*4)
        #pragma unroll
        for (int s = 16; s > 0; s >>= 1)
            #pragma unroll
            for (int i = 0; i < 8; i++)
                ss[i] += __shfl_xor_sync(0xffffffffu, ss[i], s);

        // e = exp2( sumsq * wtl2 ) = exp( diag*(wt-mw) )
        float e[8], se[8];
        #pragma unroll
        for (int i = 0; i < 8; i++) {
            e[i]  = ex2_approx(ss[i] * wtl2[i]);
            se[i] = e[i];
        }
        #pragma unroll
        for (int s = 16; s > 0; s >>= 1)
            #pragma unroll
            for (int i = 0; i < 8; i++)
                se[i] += __shfl_xor_sync(0xffffffffu, se[i], s);

        float cc[8];
        #pragma unroll
        for (int i = 0; i < 8; i++) {
            float r;
            asm("rcp.approx.ftz.f32 %0, %1;" : "=f"(r) : "f"(se[i]));
            cc[i] = e[i] * r;
        }

        {
            float* p = outC + (size_t)row * 256 + f * 8;
            __stcs(reinterpret_cast<float4*>(p),
                   make_float4(cc[0], cc[1], cc[2], cc[3]));
            __stcs(reinterpret_cast<float4*>(p + 4),
                   make_float4(cc[4], cc[5], cc[6], cc[7]));
        }
    }
}

extern "C" void kernel_launch(void* const* d_in, const int* in_sizes, int n_in,
                              void* d_out, int out_size)
{
    const float* U  = (const float*)d_in[0];   // U_hat
    const float* Wt = (const float*)d_in[1];   // W_t
    const float* Wa = (const float*)d_in[2];   // W_affine
    float* outC = (float*)d_out;
    float* outU = (float*)d_out + OUT_ELEMS;

    mhsa_kernel<<<NBLOCKS, WPB * 32>>>(U, Wt, Wa, outC, outU);
}

// round 12
// speedup vs baseline: 1.4288x; 1.0658x over previous
#include <cuda_runtime.h>

// Shapes (fixed):
// U_hat:   (32,14,14,2,16,32)  = 6,422,528 f32   -> NROWS=200704 rows of 32 (f)
// W_t:     (2,16,32,8)         = 8,192 f32       -> 32 slices (nc*dc) of [f=32][i=8]
// W_affine:(2,16,32,8)         = 8,192 f32
// Output:  C (NROWS,32,8) then U_hat_I (NROWS,32,8), concatenated.
//
// Lane mapping: lane = q*8 + i  (i = lane&7 -> output index, q = lane>>3).
// Each lane owns f = q*8+j, j=0..7 for its single i. Reductions over f =
// 7 register adds + 2 shuffles (xor 8, xor 16). Only 4 shuffles per row.
#define NROWS          200704
#define OUT_ELEMS      51380224   // NROWS*256
#define ROWS_PER_SLICE 6272       // NROWS/32
#define NBLOCKS        1184       // 148 SMs * 8
#define WPB            8
#define NWARPS         (NBLOCKS*WPB)          // 9472
#define WARPS_PER_SLICE (NWARPS/32)           // 296

__device__ __forceinline__ float ex2_approx(float x) {
    float r;
    asm("ex2.approx.ftz.f32 %0, %1;" : "=f"(r) : "f"(x));
    return r;
}
__device__ __forceinline__ float rcp_approx(float x) {
    float r;
    asm("rcp.approx.ftz.f32 %0, %1;" : "=f"(r) : "f"(x));
    return r;
}

__global__ __launch_bounds__(256, 6)
void mhsa_kernel(const float* __restrict__ U,
                 const float* __restrict__ Wt,
                 const float* __restrict__ Wa,
                 float* __restrict__ outC,
                 float* __restrict__ outU)
{
    const int w = blockIdx.x * WPB + (threadIdx.x >> 5);  // 0..9471
    const int lane = threadIdx.x & 31;
    const int i = lane & 7;      // output index i
    const int q = lane >> 3;     // f-quadrant: f = q*8 + j
    const int c = w & 31;        // (nc,dc) slice
    const int g = w >> 5;        // warp-within-slice 0..295

    // ---- one-time per warp: weights into registers (lane's column i, 8 f's) ----
    float wa_l[8], wt_l[8];
    {
        const float* wbase_a = Wa + c * 256 + (q * 8) * 8 + i;
        const float* wbase_t = Wt + c * 256 + (q * 8) * 8 + i;
        #pragma unroll
        for (int j = 0; j < 8; j++) {
            wa_l[j] = wbase_a[j * 8];
            wt_l[j] = wbase_t[j * 8];
        }
    }

    // max over all f of Wt[:,i]: local max over 8, then 2-stage shuffle max
    float mw = wt_l[0];
    #pragma unroll
    for (int j = 1; j < 8; j++) mw = fmaxf(mw, wt_l[j]);
    mw = fmaxf(mw, __shfl_xor_sync(0xffffffffu, mw, 8));
    mw = fmaxf(mw, __shfl_xor_sync(0xffffffffu, mw, 16));

    // wtl2[j] = 0.25*log2(e)*(wt-mw); diag>=0 so max_f A = diag*max_f Wt
    float wtl2[8];
    const float kconst = 0.25f * 1.4426950408889634f;
    #pragma unroll
    for (int j = 0; j < 8; j++) wtl2[j] = kconst * (wt_l[j] - mw);

    // per-lane output base offset: row*256 + (q*8+j)*8 + i = row*256 + q*64 + j*8 + i
    const int obase = q * 64 + i;

    // ---- stream rows of this slice: row = kk*32 + c ----
    #pragma unroll 2
    for (int kk = g; kk < ROWS_PER_SLICE; kk += WARPS_PER_SLICE) {
        const int row = (kk << 5) + c;

        // load lane's 8 u values (same-q lanes read identical addrs -> broadcast)
        const float4* up = reinterpret_cast<const float4*>(U + (size_t)row * 32 + q * 8);
        const float4 ua = __ldcs(up);
        const float4 ub = __ldcs(up + 1);
        const float u[8] = {ua.x, ua.y, ua.z, ua.w, ub.x, ub.y, ub.z, ub.w};

        // uhi[j] = u_f * wa[f,i]; store U_hat_I (per-j warp stores are 4 dense
        // 32B runs -> fully sector-coalesced)
        float uhi[8];
        float* pu = outU + (size_t)row * 256 + obase;
        #pragma unroll
        for (int j = 0; j < 8; j++) {
            uhi[j] = u[j] * wa_l[j];
            __stcs(pu + j * 8, uhi[j]);
        }

        // ssq_i = sum_f uhi^2 : 8 local + 2 shuffles
        float s = uhi[0] * uhi[0];
        #pragma unroll
        for (int j = 1; j < 8; j++) s = fmaf(uhi[j], uhi[j], s);
        s += __shfl_xor_sync(0xffffffffu, s, 8);
        s += __shfl_xor_sync(0xffffffffu, s, 16);

        // e[f,i] = exp2(ssq * wtl2[f,i]); se_i = sum_f e : 7 local adds + 2 shuffles
        float e[8];
        #pragma unroll
        for (int j = 0; j < 8; j++) e[j] = ex2_approx(s * wtl2[j]);
        float se = e[0];
        #pragma unroll
        for (int j = 1; j < 8; j++) se += e[j];
        se += __shfl_xor_sync(0xffffffffu, se, 8);
        se += __shfl_xor_sync(0xffffffffu, se, 16);

        const float r = rcp_approx(se);
        float* pc = outC + (size_t)row * 256 + obase;
        #pragma unroll
        for (int j = 0; j < 8; j++)
            __stcs(pc + j * 8, e[j] * r);
    }
}

extern "C" void kernel_launch(void* const* d_in, const int* in_sizes, int n_in,
                              void* d_out, int out_size)
{
    const float* U  = (const float*)d_in[0];   // U_hat
    const float* Wt = (const float*)d_in[1];   // W_t
    const float* Wa = (const float*)d_in[2];   // W_affine
    float* outC = (float*)d_out;
    float* outU = (float*)d_out + OUT_ELEMS;

    mhsa_kernel<<<NBLOCKS, WPB * 32>>>(U, Wt, Wa, outC, outU);
}

// round 15
// speedup vs baseline: 1.5070x; 1.0547x over previous
#include <cuda_runtime.h>

// Shapes (fixed):
// U_hat:   (32,14,14,2,16,32)  = 6,422,528 f32   -> NROWS=200704 rows of 32 (f)
// W_t:     (2,16,32,8)         = 8,192 f32       -> 32 slices (nc*dc) of [f=32][i=8]
// W_affine:(2,16,32,8)         = 8,192 f32
// Output:  C (NROWS,32,8) then U_hat_I (NROWS,32,8), concatenated.
//
// Lane mapping: lane = q*8 + i  (i = lane&7 -> output index, q = lane>>3).
// Each lane owns f = q*8+j, j=0..7 for its single i. Reductions over f =
// 7 register adds + 2 shuffles (xor 8, xor 16). Only 4 shuffles per row.
#define NROWS          200704
#define OUT_ELEMS      51380224   // NROWS*256
#define ROWS_PER_SLICE 6272       // NROWS/32
#define NBLOCKS        1184       // 148 SMs * 8
#define WPB            8
#define NWARPS         (NBLOCKS*WPB)          // 9472
#define WARPS_PER_SLICE (NWARPS/32)           // 296

__device__ __forceinline__ float ex2_approx(float x) {
    float r;
    asm("ex2.approx.ftz.f32 %0, %1;" : "=f"(r) : "f"(x));
    return r;
}
__device__ __forceinline__ float rcp_approx(float x) {
    float r;
    asm("rcp.approx.ftz.f32 %0, %1;" : "=f"(r) : "f"(x));
    return r;
}

__global__ __launch_bounds__(256, 6)
void mhsa_kernel(const float* __restrict__ U,
                 const float* __restrict__ Wt,
                 const float* __restrict__ Wa,
                 float* __restrict__ outC,
                 float* __restrict__ outU)
{
    const int w = blockIdx.x * WPB + (threadIdx.x >> 5);  // 0..9471
    const int lane = threadIdx.x & 31;
    const int i = lane & 7;      // output index i
    const int q = lane >> 3;     // f-quadrant: f = q*8 + j
    const int c = w & 31;        // (nc,dc) slice
    const int g = w >> 5;        // warp-within-slice 0..295

    // ---- one-time per warp: weights into registers (lane's column i, 8 f's) ----
    float wa_l[8], wt_l[8];
    {
        const float* wbase_a = Wa + c * 256 + (q * 8) * 8 + i;
        const float* wbase_t = Wt + c * 256 + (q * 8) * 8 + i;
        #pragma unroll
        for (int j = 0; j < 8; j++) {
            wa_l[j] = wbase_a[j * 8];
            wt_l[j] = wbase_t[j * 8];
        }
    }

    // max over all f of Wt[:,i]: local max over 8, then 2-stage shuffle max
    float mw = wt_l[0];
    #pragma unroll
    for (int j = 1; j < 8; j++) mw = fmaxf(mw, wt_l[j]);
    mw = fmaxf(mw, __shfl_xor_sync(0xffffffffu, mw, 8));
    mw = fmaxf(mw, __shfl_xor_sync(0xffffffffu, mw, 16));

    // wtl2[j] = 0.25*log2(e)*(wt-mw); diag>=0 so max_f A = diag*max_f Wt
    float wtl2[8];
    const float kconst = 0.25f * 1.4426950408889634f;
    #pragma unroll
    for (int j = 0; j < 8; j++) wtl2[j] = kconst * (wt_l[j] - mw);

    // per-lane output base offset: row*256 + (q*8+j)*8 + i = row*256 + q*64 + j*8 + i
    const int obase = q * 64 + i;

    // ---- stream rows of this slice: row = kk*32 + c ----
    #pragma unroll 2
    for (int kk = g; kk < ROWS_PER_SLICE; kk += WARPS_PER_SLICE) {
        const int row = (kk << 5) + c;

        // load lane's 8 u values (same-q lanes read identical addrs -> broadcast)
        const float4* up = reinterpret_cast<const float4*>(U + (size_t)row * 32 + q * 8);
        const float4 ua = __ldcs(up);
        const float4 ub = __ldcs(up + 1);
        const float u[8] = {ua.x, ua.y, ua.z, ua.w, ub.x, ub.y, ub.z, ub.w};

        // uhi[j] = u_f * wa[f,i]; store U_hat_I (per-j warp stores are 4 dense
        // 32B runs -> fully sector-coalesced)
        float uhi[8];
        float* pu = outU + (size_t)row * 256 + obase;
        #pragma unroll
        for (int j = 0; j < 8; j++) {
            uhi[j] = u[j] * wa_l[j];
            __stcs(pu + j * 8, uhi[j]);
        }

        // ssq_i = sum_f uhi^2 : 8 local + 2 shuffles
        float s = uhi[0] * uhi[0];
        #pragma unroll
        for (int j = 1; j < 8; j++) s = fmaf(uhi[j], uhi[j], s);
        s += __shfl_xor_sync(0xffffffffu, s, 8);
        s += __shfl_xor_sync(0xffffffffu, s, 16);

        // e[f,i] = exp2(ssq * wtl2[f,i]); se_i = sum_f e : 7 local adds + 2 shuffles
        float e[8];
        #pragma unroll
        for (int j = 0; j < 8; j++) e[j] = ex2_approx(s * wtl2[j]);
        float se = e[0];
        #pragma unroll
        for (int j = 1; j < 8; j++) se += e[j];
        se += __shfl_xor_sync(0xffffffffu, se, 8);
        se += __shfl_xor_sync(0xffffffffu, se, 16);

        const float r = rcp_approx(se);
        float* pc = outC + (size_t)row * 256 + obase;
        #pragma unroll
        for (int j = 0; j < 8; j++)
            __stcs(pc + j * 8, e[j] * r);
    }
}

extern "C" void kernel_launch(void* const* d_in, const int* in_sizes, int n_in,
                              void* d_out, int out_size)
{
    const float* U  = (const float*)d_in[0];   // U_hat
    const float* Wt = (const float*)d_in[1];   // W_t
    const float* Wa = (const float*)d_in[2];   // W_affine
    float* outC = (float*)d_out;
    float* outU = (float*)d_out + OUT_ELEMS;

    mhsa_kernel<<<NBLOCKS, WPB * 32>>>(U, Wt, Wa, outC, outU);
}